// round 10
// baseline (speedup 1.0000x reference)
#include <cuda_runtime.h>
#include <cuda_bf16.h>
#include <math.h>

#define PN 20
#define GB 8          // batches per CTA iteration (one per warp)

__device__ __forceinline__ void stg_v8(float* p, const float* o) {
    asm volatile("st.global.v8.b32 [%0], {%1,%2,%3,%4,%5,%6,%7,%8};"
        :: "l"(p),
           "r"(__float_as_uint(o[0])), "r"(__float_as_uint(o[1])),
           "r"(__float_as_uint(o[2])), "r"(__float_as_uint(o[3])),
           "r"(__float_as_uint(o[4])), "r"(__float_as_uint(o[5])),
           "r"(__float_as_uint(o[6])), "r"(__float_as_uint(o[7]))
        : "memory");
}

__global__ __launch_bounds__(256, 4)
void spf_kernel(const float* __restrict__ points,
                const float* __restrict__ mask,
                const float* __restrict__ W_rel,     // [3,64]
                const float* __restrict__ b_rel,     // [64]
                const float* __restrict__ W_dist,    // [1,64]
                const float* __restrict__ b_dist,    // [64]
                const float* __restrict__ emb_count, // [50,64]
                const float* __restrict__ W_den,     // [1,64]
                const float* __restrict__ b_den,     // [64]
                float* __restrict__ out,             // [B,20,256]
                int B)
{
    // per-point scalar bundle: {rx,ry,rz,cd,dens,0,0,0}
    __shared__ float sv[GB][PN][8];
    __shared__ float semb[GB][64];

    const int t    = threadIdx.x;
    const int lane = t & 31;
    const int w    = t >> 5;
    const long long stride = (long long)gridDim.x * GB;

    // ---------- store-role constants + weights (ONCE per persistent CTA) ----
    const int j8 = t & 31;
    const int g  = j8 >> 3;          // 0=rel, 1=dist, 2=count, 3=den
    const int lc = (j8 & 7) * 8;
    const int n0 = t >> 5;           // rows n0, n0+8, (n0+16 if n0<4)
    const int i1 = (g == 0) ? 0 : ((g == 1) ? 3 : ((g == 3) ? 4 : 5));
    const int i2 = (g == 0) ? 1 : 5;
    const int i3 = (g == 0) ? 2 : 5;

    float P[8], Q[8], R[8], F[8];
    #pragma unroll
    for (int q = 0; q < 8; q++) {
        int c = lc + q;
        float p_, f_;
        if (g == 0)      { p_ = __ldg(W_rel + c);  f_ = __ldg(b_rel + c);  }
        else if (g == 1) { p_ = __ldg(W_dist + c); f_ = __ldg(b_dist + c); }
        else if (g == 3) { p_ = __ldg(W_den + c);  f_ = __ldg(b_den + c);  }
        else             { p_ = 0.f;               f_ = 0.f;               }
        P[q] = p_;
        Q[q] = (g == 0) ? __ldg(W_rel + 64 + c)  : 0.f;
        R[q] = (g == 0) ? __ldg(W_rel + 128 + c) : 0.f;
        F[q] = f_;
    }
    const bool row3 = (n0 < PN - 16);

    // ---------- prefetch first iteration's points ----------
    long long b0 = (long long)blockIdx.x * GB;
    float px = 0.f, py = 0.f, pz = 0.f, m = 0.f;
    if (b0 + w < B && lane < PN) {
        const float* pp = points + (b0 + w) * (PN * 3) + lane * 3;
        px = pp[0]; py = pp[1]; pz = pp[2];
        m  = mask[(b0 + w) * PN + lane];
    }

    for (; b0 < B; b0 += stride) {
        // ============ compute phase: warp w owns batch b0+w ============
        if (b0 + w < B) {
            float nvf = m, cx = m * px, cy = m * py, cz = m * pz;
            #pragma unroll
            for (int o = 16; o > 0; o >>= 1) {
                nvf += __shfl_xor_sync(0xffffffffu, nvf, o);
                cx  += __shfl_xor_sync(0xffffffffu, cx,  o);
                cy  += __shfl_xor_sync(0xffffffffu, cy,  o);
                cz  += __shfl_xor_sync(0xffffffffu, cz,  o);
            }
            int nvi = (int)(nvf + 0.5f);
            int nvc = nvi < 1 ? 1 : nvi;
            float inv = 1.f / (float)nvc;
            cx *= inv; cy *= inv; cz *= inv;

            float rx = px - cx, ry = py - cy, rz = pz - cz;
            float cd = sqrtf(rx * rx + ry * ry + rz * rz);

            float e0 = 3e38f, e1 = 3e38f, e2 = 3e38f;
            #pragma unroll
            for (int j = 0; j < PN; j++) {
                float qx = __shfl_sync(0xffffffffu, px, j);
                float qy = __shfl_sync(0xffffffffu, py, j);
                float qz = __shfl_sync(0xffffffffu, pz, j);
                float mj = __shfl_sync(0xffffffffu, m,  j);
                float dx = px - qx, dy = py - qy, dz = pz - qz;
                float d2 = fmaxf(dx * dx + dy * dy + dz * dz, 1e-12f);
                if (j == lane || mj <= 0.f) d2 = 3e38f;
                if (d2 < e0)      { e2 = e1; e1 = e0; e0 = d2; }
                else if (d2 < e1) { e2 = e1; e1 = d2; }
                else if (d2 < e2) { e2 = d2; }
            }
            float dens = 0.f;
            if (m > 0.f && nvi > 1) {
                int k = nvi - 1; if (k > 3) k = 3;
                float s = sqrtf(e0);
                if (k > 1) s += sqrtf(e1);
                if (k > 2) s += sqrtf(e2);
                dens = s / (float)k;
            }

            if (lane < PN) {
                float* d = sv[w][lane];
                d[0] = rx; d[1] = ry; d[2] = rz; d[3] = cd;
                d[4] = dens; d[5] = 0.f; d[6] = 0.f; d[7] = 0.f;
            }
            semb[w][lane]      = __ldg(emb_count + (size_t)nvc * 64 + lane);
            semb[w][lane + 32] = __ldg(emb_count + (size_t)nvc * 64 + lane + 32);
        }
        __syncthreads();

        // ---- prefetch next iteration's points (drains under store burst) ----
        long long bn = b0 + stride + w;
        px = 0.f; py = 0.f; pz = 0.f; m = 0.f;
        if (bn < B && lane < PN) {
            const float* pp = points + bn * (PN * 3) + lane * 3;
            px = pp[0]; py = pp[1]; pz = pp[2];
            m  = mask[bn * PN + lane];
        }

        // ============ store phase: branch-free unified epilogue ============
        float Floc[8];
        #pragma unroll
        for (int q = 0; q < 8; q++) Floc[q] = F[q];
        float* outB = out + (size_t)b0 * (PN * 256);
        #pragma unroll
        for (int w2 = 0; w2 < GB; w2++) {
            if (b0 + w2 >= B) break;
            if (g == 2) {
                #pragma unroll
                for (int q = 0; q < 8; q++) Floc[q] = semb[w2][lc + q];
            }
            float* obw = outB + (size_t)w2 * (PN * 256);
            #pragma unroll
            for (int r = 0; r < 3; r++) {
                if (r == 2 && !row3) break;
                int n = n0 + 8 * r;
                const float* s = sv[w2][n];
                float s1 = s[i1], s2 = s[i2], s3 = s[i3];
                float o[8];
                #pragma unroll
                for (int q = 0; q < 8; q++)
                    o[q] = fmaf(s1, P[q], fmaf(s2, Q[q], fmaf(s3, R[q], Floc[q])));
                stg_v8(obw + n * 256 + j8 * 8, o);
            }
        }
        __syncthreads();   // sv/semb reuse fence before next compute
    }
}

extern "C" void kernel_launch(void* const* d_in, const int* in_sizes, int n_in,
                              void* d_out, int out_size) {
    const float* points    = (const float*)d_in[0];
    const float* mask      = (const float*)d_in[1];
    const float* W_rel     = (const float*)d_in[2];
    const float* b_rel     = (const float*)d_in[3];
    const float* W_dist    = (const float*)d_in[4];
    const float* b_dist    = (const float*)d_in[5];
    const float* emb_count = (const float*)d_in[6];
    const float* W_den     = (const float*)d_in[7];
    const float* b_den     = (const float*)d_in[8];
    float* out = (float*)d_out;

    int B = in_sizes[0] / (PN * 3);
    int ctasNeeded = (B + GB - 1) / GB;
    int grid = 4 * 148;                 // persistent: occupancy * SM count
    if (grid > ctasNeeded) grid = ctasNeeded;
    spf_kernel<<<grid, 256>>>(points, mask, W_rel, b_rel, W_dist, b_dist,
                              emb_count, W_den, b_den, out, B);
}

// round 11
// speedup vs baseline: 1.1912x; 1.1912x over previous
#include <cuda_runtime.h>
#include <cuda_bf16.h>
#include <math.h>

#define PN 20
#define GB 8          // batches per CTA (one per warp)

__device__ __forceinline__ void stg_v8(float* p, const float* o) {
    asm volatile("st.global.v8.b32 [%0], {%1,%2,%3,%4,%5,%6,%7,%8};"
        :: "l"(p),
           "r"(__float_as_uint(o[0])), "r"(__float_as_uint(o[1])),
           "r"(__float_as_uint(o[2])), "r"(__float_as_uint(o[3])),
           "r"(__float_as_uint(o[4])), "r"(__float_as_uint(o[5])),
           "r"(__float_as_uint(o[6])), "r"(__float_as_uint(o[7]))
        : "memory");
}

__global__ __launch_bounds__(256, 4)
void spf_kernel(const float* __restrict__ points,
                const float* __restrict__ mask,
                const float* __restrict__ W_rel,     // [3,64]
                const float* __restrict__ b_rel,     // [64]
                const float* __restrict__ W_dist,    // [1,64]
                const float* __restrict__ b_dist,    // [64]
                const float* __restrict__ emb_count, // [50,64]
                const float* __restrict__ W_den,     // [1,64]
                const float* __restrict__ b_den,     // [64]
                float* __restrict__ out,             // [B,20,256]
                int B)
{
    // per-point scalar bundle: {rx,ry,rz,cd,dens,0,0,0}
    __shared__ float sv[GB][PN][8];
    __shared__ float semb[GB][64];

    const int t    = threadIdx.x;
    const int lane = t & 31;
    const int w    = t >> 5;
    const long long b0 = (long long)blockIdx.x * GB;

    // ================= compute phase: warp w owns batch b0+w =================
    if (b0 + w < B) {
        const long long b = b0 + w;
        float px = 0.f, py = 0.f, pz = 0.f, m = 0.f;
        if (lane < PN) {
            const float* pp = points + b * (PN * 3) + lane * 3;
            px = pp[0]; py = pp[1]; pz = pp[2];
            m  = mask[b * PN + lane];
        }
        // valid count + centroid
        float nvf = m, cx = m * px, cy = m * py, cz = m * pz;
        #pragma unroll
        for (int o = 16; o > 0; o >>= 1) {
            nvf += __shfl_xor_sync(0xffffffffu, nvf, o);
            cx  += __shfl_xor_sync(0xffffffffu, cx,  o);
            cy  += __shfl_xor_sync(0xffffffffu, cy,  o);
            cz  += __shfl_xor_sync(0xffffffffu, cz,  o);
        }
        int nvi = (int)(nvf + 0.5f);
        int nvc = nvi < 1 ? 1 : nvi;
        float inv = 1.f / (float)nvc;
        cx *= inv; cy *= inv; cz *= inv;

        float rx = px - cx, ry = py - cy, rz = pz - cz;
        float cd = sqrtf(rx * rx + ry * ry + rz * rz);

        // top-3 nearest neighbors on SQUARED distances (sqrt deferred to 3)
        float e0 = 3e38f, e1 = 3e38f, e2 = 3e38f;
        #pragma unroll
        for (int j = 0; j < PN; j++) {
            float qx = __shfl_sync(0xffffffffu, px, j);
            float qy = __shfl_sync(0xffffffffu, py, j);
            float qz = __shfl_sync(0xffffffffu, pz, j);
            float mj = __shfl_sync(0xffffffffu, m,  j);
            float dx = px - qx, dy = py - qy, dz = pz - qz;
            float d2 = fmaxf(dx * dx + dy * dy + dz * dz, 1e-12f);
            if (j == lane || mj <= 0.f) d2 = 3e38f;
            if (d2 < e0)      { e2 = e1; e1 = e0; e0 = d2; }
            else if (d2 < e1) { e2 = e1; e1 = d2; }
            else if (d2 < e2) { e2 = d2; }
        }
        float dens = 0.f;
        if (m > 0.f && nvi > 1) {
            int k = nvi - 1; if (k > 3) k = 3;
            float s = sqrtf(e0);
            if (k > 1) s += sqrtf(e1);
            if (k > 2) s += sqrtf(e2);
            dens = s / (float)k;
        }

        if (lane < PN) {
            float* d = sv[w][lane];
            d[0] = rx; d[1] = ry; d[2] = rz; d[3] = cd;
            d[4] = dens; d[5] = 0.f; d[6] = 0.f; d[7] = 0.f;
        }
        semb[w][lane]      = __ldg(emb_count + (size_t)nvc * 64 + lane);
        semb[w][lane + 32] = __ldg(emb_count + (size_t)nvc * 64 + lane + 32);
    }
    __syncthreads();

    // ================= store phase: branch-free unified epilogue =============
    // thread owns fixed 8-channel chunk j8 (32B); rows n0, n0+8, (n0+16 if n0<4)
    const int j8 = t & 31;
    const int g  = j8 >> 3;          // 0=rel, 1=dist, 2=count, 3=den
    const int lc = (j8 & 7) * 8;     // channel base within group
    const int n0 = t >> 5;           // 0..7

    // scalar selection indices into sv[.][n][8] (slot 5 is always 0)
    const int i1 = (g == 0) ? 0 : ((g == 1) ? 3 : ((g == 3) ? 4 : 5));
    const int i2 = (g == 0) ? 1 : 5;
    const int i3 = (g == 0) ? 2 : 5;

    // per-lane weights: o = s1*P + s2*Q + s3*R + F
    float P[8], Q[8], R[8], F[8];
    #pragma unroll
    for (int q = 0; q < 8; q++) {
        int c = lc + q;
        float p_, f_;
        if (g == 0)      { p_ = __ldg(W_rel + c);  f_ = __ldg(b_rel + c);  }
        else if (g == 1) { p_ = __ldg(W_dist + c); f_ = __ldg(b_dist + c); }
        else if (g == 3) { p_ = __ldg(W_den + c);  f_ = __ldg(b_den + c);  }
        else             { p_ = 0.f;               f_ = 0.f;               }
        P[q] = p_;
        Q[q] = (g == 0) ? __ldg(W_rel + 64 + c)  : 0.f;
        R[q] = (g == 0) ? __ldg(W_rel + 128 + c) : 0.f;
        F[q] = f_;
    }

    const bool row3 = (n0 < PN - 16);   // n0 < 4
    float* outB = out + (size_t)b0 * (PN * 256);
    #pragma unroll
    for (int w2 = 0; w2 < GB; w2++) {
        if (b0 + w2 >= B) break;
        if (g == 2) {
            #pragma unroll
            for (int q = 0; q < 8; q++) F[q] = semb[w2][lc + q];
        }
        float* obw = outB + (size_t)w2 * (PN * 256);
        #pragma unroll
        for (int r = 0; r < 3; r++) {
            if (r == 2 && !row3) break;
            int n = n0 + 8 * r;
            const float* s = sv[w2][n];
            float s1 = s[i1], s2 = s[i2], s3 = s[i3];
            float o[8];
            #pragma unroll
            for (int q = 0; q < 8; q++)
                o[q] = fmaf(s1, P[q], fmaf(s2, Q[q], fmaf(s3, R[q], F[q])));
            stg_v8(obw + n * 256 + j8 * 8, o);
        }
    }
}

extern "C" void kernel_launch(void* const* d_in, const int* in_sizes, int n_in,
                              void* d_out, int out_size) {
    const float* points    = (const float*)d_in[0];
    const float* mask      = (const float*)d_in[1];
    const float* W_rel     = (const float*)d_in[2];
    const float* b_rel     = (const float*)d_in[3];
    const float* W_dist    = (const float*)d_in[4];
    const float* b_dist    = (const float*)d_in[5];
    const float* emb_count = (const float*)d_in[6];
    const float* W_den     = (const float*)d_in[7];
    const float* b_den     = (const float*)d_in[8];
    float* out = (float*)d_out;

    int B = in_sizes[0] / (PN * 3);
    int grid = (B + GB - 1) / GB;
    spf_kernel<<<grid, 256>>>(points, mask, W_rel, b_rel, W_dist, b_dist,
                              emb_count, W_den, b_den, out, B);
}

// round 12
// speedup vs baseline: 1.1988x; 1.0064x over previous
#include <cuda_runtime.h>
#include <cuda_bf16.h>
#include <math.h>

#define PN 20
#define GB 4           // batches per CTA (one per warp)
#define THR 128

__device__ __forceinline__ void stg_v8(float* p, const float* o) {
    asm volatile("st.global.v8.b32 [%0], {%1,%2,%3,%4,%5,%6,%7,%8};"
        :: "l"(p),
           "r"(__float_as_uint(o[0])), "r"(__float_as_uint(o[1])),
           "r"(__float_as_uint(o[2])), "r"(__float_as_uint(o[3])),
           "r"(__float_as_uint(o[4])), "r"(__float_as_uint(o[5])),
           "r"(__float_as_uint(o[6])), "r"(__float_as_uint(o[7]))
        : "memory");
}

__global__ __launch_bounds__(THR, 8)
void spf_kernel(const float* __restrict__ points,
                const float* __restrict__ mask,
                const float* __restrict__ W_rel,     // [3,64]
                const float* __restrict__ b_rel,     // [64]
                const float* __restrict__ W_dist,    // [1,64]
                const float* __restrict__ b_dist,    // [64]
                const float* __restrict__ emb_count, // [50,64]
                const float* __restrict__ W_den,     // [1,64]
                const float* __restrict__ b_den,     // [64]
                float* __restrict__ out,             // [B,20,256]
                int B)
{
    // per-point scalar bundle: {rx,ry,rz,cd,dens,0,0,0}
    __shared__ float sv[GB][PN][8];
    __shared__ float semb[GB][64];

    const int t    = threadIdx.x;
    const int lane = t & 31;
    const int w    = t >> 5;
    const long long b0 = (long long)blockIdx.x * GB;

    // ================= compute phase: warp w owns batch b0+w =================
    if (b0 + w < B) {
        const long long b = b0 + w;
        float px = 0.f, py = 0.f, pz = 0.f, m = 0.f;
        if (lane < PN) {
            const float* pp = points + b * (PN * 3) + lane * 3;
            px = pp[0]; py = pp[1]; pz = pp[2];
            m  = mask[b * PN + lane];
        }
        // valid count + centroid
        float nvf = m, cx = m * px, cy = m * py, cz = m * pz;
        #pragma unroll
        for (int o = 16; o > 0; o >>= 1) {
            nvf += __shfl_xor_sync(0xffffffffu, nvf, o);
            cx  += __shfl_xor_sync(0xffffffffu, cx,  o);
            cy  += __shfl_xor_sync(0xffffffffu, cy,  o);
            cz  += __shfl_xor_sync(0xffffffffu, cz,  o);
        }
        int nvi = (int)(nvf + 0.5f);
        int nvc = nvi < 1 ? 1 : nvi;
        float inv = 1.f / (float)nvc;
        cx *= inv; cy *= inv; cz *= inv;

        float rx = px - cx, ry = py - cy, rz = pz - cz;
        float cd = sqrtf(rx * rx + ry * ry + rz * rz);

        // top-3 nearest neighbors on SQUARED distances (sqrt deferred to 3)
        float e0 = 3e38f, e1 = 3e38f, e2 = 3e38f;
        #pragma unroll
        for (int j = 0; j < PN; j++) {
            float qx = __shfl_sync(0xffffffffu, px, j);
            float qy = __shfl_sync(0xffffffffu, py, j);
            float qz = __shfl_sync(0xffffffffu, pz, j);
            float mj = __shfl_sync(0xffffffffu, m,  j);
            float dx = px - qx, dy = py - qy, dz = pz - qz;
            float d2 = fmaxf(dx * dx + dy * dy + dz * dz, 1e-12f);
            if (j == lane || mj <= 0.f) d2 = 3e38f;
            if (d2 < e0)      { e2 = e1; e1 = e0; e0 = d2; }
            else if (d2 < e1) { e2 = e1; e1 = d2; }
            else if (d2 < e2) { e2 = d2; }
        }
        float dens = 0.f;
        if (m > 0.f && nvi > 1) {
            int k = nvi - 1; if (k > 3) k = 3;
            float s = sqrtf(e0);
            if (k > 1) s += sqrtf(e1);
            if (k > 2) s += sqrtf(e2);
            dens = s / (float)k;
        }

        if (lane < PN) {
            float* d = sv[w][lane];
            d[0] = rx; d[1] = ry; d[2] = rz; d[3] = cd;
            d[4] = dens; d[5] = 0.f; d[6] = 0.f; d[7] = 0.f;
        }
        semb[w][lane]      = __ldg(emb_count + (size_t)nvc * 64 + lane);
        semb[w][lane + 32] = __ldg(emb_count + (size_t)nvc * 64 + lane + 32);
    }
    __syncthreads();

    // ================= store phase: branch-free unified epilogue =============
    // thread owns fixed 8-channel chunk j8 (32B); rows n0+4r, r=0..4
    const int j8 = t & 31;
    const int g  = j8 >> 3;          // 0=rel, 1=dist, 2=count, 3=den
    const int lc = (j8 & 7) * 8;     // channel base within group
    const int n0 = t >> 5;           // 0..3

    // scalar selection indices into sv[.][n][8] (slot 5 is always 0)
    const int i1 = (g == 0) ? 0 : ((g == 1) ? 3 : ((g == 3) ? 4 : 5));
    const int i2 = (g == 0) ? 1 : 5;
    const int i3 = (g == 0) ? 2 : 5;

    // per-lane weights: o = s1*P + s2*Q + s3*R + F
    float P[8], Q[8], R[8], F[8];
    #pragma unroll
    for (int q = 0; q < 8; q++) {
        int c = lc + q;
        float p_, f_;
        if (g == 0)      { p_ = __ldg(W_rel + c);  f_ = __ldg(b_rel + c);  }
        else if (g == 1) { p_ = __ldg(W_dist + c); f_ = __ldg(b_dist + c); }
        else if (g == 3) { p_ = __ldg(W_den + c);  f_ = __ldg(b_den + c);  }
        else             { p_ = 0.f;               f_ = 0.f;               }
        P[q] = p_;
        Q[q] = (g == 0) ? __ldg(W_rel + 64 + c)  : 0.f;
        R[q] = (g == 0) ? __ldg(W_rel + 128 + c) : 0.f;
        F[q] = f_;
    }

    float* outB = out + (size_t)b0 * (PN * 256);
    #pragma unroll
    for (int w2 = 0; w2 < GB; w2++) {
        if (b0 + w2 >= B) break;
        if (g == 2) {
            #pragma unroll
            for (int q = 0; q < 8; q++) F[q] = semb[w2][lc + q];
        }
        float* obw = outB + (size_t)w2 * (PN * 256);
        #pragma unroll
        for (int r = 0; r < 5; r++) {
            int n = n0 + 4 * r;
            const float* s = sv[w2][n];
            float s1 = s[i1], s2 = s[i2], s3 = s[i3];
            float o[8];
            #pragma unroll
            for (int q = 0; q < 8; q++)
                o[q] = fmaf(s1, P[q], fmaf(s2, Q[q], fmaf(s3, R[q], F[q])));
            stg_v8(obw + n * 256 + j8 * 8, o);
        }
    }
}

extern "C" void kernel_launch(void* const* d_in, const int* in_sizes, int n_in,
                              void* d_out, int out_size) {
    const float* points    = (const float*)d_in[0];
    const float* mask      = (const float*)d_in[1];
    const float* W_rel     = (const float*)d_in[2];
    const float* b_rel     = (const float*)d_in[3];
    const float* W_dist    = (const float*)d_in[4];
    const float* b_dist    = (const float*)d_in[5];
    const float* emb_count = (const float*)d_in[6];
    const float* W_den     = (const float*)d_in[7];
    const float* b_den     = (const float*)d_in[8];
    float* out = (float*)d_out;

    int B = in_sizes[0] / (PN * 3);
    int grid = (B + GB - 1) / GB;
    spf_kernel<<<grid, THR>>>(points, mask, W_rel, b_rel, W_dist, b_dist,
                              emb_count, W_den, b_den, out, B);
}